// round 15
// baseline (speedup 1.0000x reference)
#include <cuda_runtime.h>

// Problem constants (B=2, N=8192 -> M=16384, fixed for this problem id)
#define MTOT   16384
#define BSHIFT 13
#define CTAS1  128        // k1: 128 rows per CTA; paired CTAs share 256 candidates
#define THR1   128
#define SPLIT  8          // k2: each survivor scanned by 8 CTAs (one part each)
#define PARTN  (MTOT / SPLIT)   // 2048 points per part
#define CTAS2  512
#define THR2   256
#define THR3   256

// ---------------- scratch (device globals; zero at module load; k3 resets
// the cross-launch counters so graph replays are deterministic) -------------
__device__ float4   g_gt[MTOT];     // gx, gy, gz, |g|^2
__device__ float4   g_sinfo[MTOT];  // survivor: (-2px, -2py, -2pz, fown)
__device__ float    g_sxv[MTOT];    // survivor's logit value
__device__ unsigned g_rmin[MTOT];   // per-survivor global min (ordered uint)
__device__ int      g_scnt;         // survivor count
__device__ float    g_acc[4];       // sum_w, sum_w_err, bce0(phaseA), cnt0(phaseA)

// canonical chains — identical instruction sequences at every use site
__device__ __forceinline__ float fchain(float ax, float ay, float az, float4 g) {
    return fmaf(ax, g.x, fmaf(ay, g.y, fmaf(az, g.z, g.w)));
}
__device__ __forceinline__ float4 pose_pt(const float* __restrict__ P,
                                          float x, float y, float z) {
    float gx = fmaf(P[0], x, fmaf(P[1], y, fmaf(P[2],  z, P[3])));
    float gy = fmaf(P[4], x, fmaf(P[5], y, fmaf(P[6],  z, P[7])));
    float gz = fmaf(P[8], x, fmaf(P[9], y, fmaf(P[10], z, P[11])));
    float sg = fmaf(gx, gx, fmaf(gy, gy, gz * gz));
    return make_float4(gx, gy, gz, sg);
}
// strictly order-preserving float -> uint map (exact comparisons preserved)
__device__ __forceinline__ unsigned fmap(float f) {
    unsigned u = __float_as_uint(f);
    return (u & 0x80000000u) ? ~u : (u | 0x80000000u);
}

// ==== K1: prep + phase A; paired CTAs share a 256-row candidate block ======
__global__ __launch_bounds__(THR1) void k1(const float* __restrict__ kb,
                                           const float* __restrict__ kw,
                                           const float* __restrict__ pg,
                                           const float* __restrict__ ow,
                                           const float* __restrict__ lg) {
    __shared__ __align__(16) float4 s_gt[2 * THR1];      // 4 KB: pair block
    __shared__ float s_r4[4][THR1 / 32];
    int tid = threadIdx.x, lane = tid & 31, wid = tid >> 5;
    int row  = blockIdx.x * THR1 + tid;
    int prow = (blockIdx.x ^ 1) * THR1 + tid;   // partner CTA's row (coalesced)
    int half = blockIdx.x & 1;

    g_rmin[row] = 0xFFFFFFFFu;               // re-arm k2's min slots each launch

    // pose matrix: pair block never straddles the batch boundary (8192%256==0)
    const float* P = pg + (row >> BSHIFT) * 12;
    float4 gt  = pose_pt(P, kb[3 * row],  kb[3 * row + 1],  kb[3 * row + 2]);
    float4 pgt = pose_pt(P, kb[3 * prow], kb[3 * prow + 1], kb[3 * prow + 2]);
    s_gt[half * THR1 + tid] = gt;            // own half of the pair block
    s_gt[(1 - half) * THR1 + tid] = pgt;     // partner half (recomputed, exact)
    g_gt[row] = gt;                          // k2's scan table (own rows only)

    float px = kw[3 * row], py = kw[3 * row + 1], pz = kw[3 * row + 2];
    float ax = -2.0f * px, ay = -2.0f * py, az = -2.0f * pz;
    float fo = fchain(ax, ay, az, gt);

    float w = ow[row];
    float xv = lg[row];
    float swe = w * (fabsf(px - gt.x) + fabsf(py - gt.y) + fabsf(pz - gt.z));
    float sw = w;
    __syncthreads();                         // publish s_gt

    // phase A: 256 pair-block candidates (j==row reproduces fo, never < fo)
    const float INF = __int_as_float(0x7f800000);
    float m0 = INF, m1 = INF, m2 = INF, m3 = INF;
    #pragma unroll 8
    for (int k = 0; k < 2 * THR1; k += 4) {
        m0 = fminf(m0, fchain(ax, ay, az, s_gt[k + 0]));
        m1 = fminf(m1, fchain(ax, ay, az, s_gt[k + 1]));
        m2 = fminf(m2, fchain(ax, ay, az, s_gt[k + 2]));
        m3 = fminf(m3, fchain(ax, ay, az, s_gt[k + 3]));
    }
    float mn = fminf(fminf(m0, m1), fminf(m2, m3));

    float s0 = 0.f, c0 = 0.f;
    if (mn < fo) {                           // strictly closer -> mask = 0
        float lp = log1pf(expf(-fabsf(xv)));
        s0 = fmaxf(xv, 0.f) + lp;            // softplus(x), label 0
        c0 = 1.f;
    } else {                                 // unresolved -> exact scan in k2
        int pos = atomicAdd(&g_scnt, 1);
        g_sinfo[pos] = make_float4(ax, ay, az, fo);
        g_sxv[pos] = xv;
    }

    // fused 4-quantity CTA reduction -> one atomicAdd set per CTA
    #pragma unroll
    for (int off = 16; off; off >>= 1) {
        sw  += __shfl_down_sync(0xffffffffu, sw,  off);
        swe += __shfl_down_sync(0xffffffffu, swe, off);
        s0  += __shfl_down_sync(0xffffffffu, s0,  off);
        c0  += __shfl_down_sync(0xffffffffu, c0,  off);
    }
    if (lane == 0) {
        s_r4[0][wid] = sw;  s_r4[1][wid] = swe;
        s_r4[2][wid] = s0;  s_r4[3][wid] = c0;
    }
    __syncthreads();
    if (tid == 0) {
        float a = 0.f, b = 0.f, c = 0.f, d = 0.f;
        #pragma unroll
        for (int k = 0; k < THR1 / 32; k++) {
            a += s_r4[0][k]; b += s_r4[1][k]; c += s_r4[2][k]; d += s_r4[3][k];
        }
        atomicAdd(&g_acc[0], a); atomicAdd(&g_acc[1], b);
        atomicAdd(&g_acc[2], c); atomicAdd(&g_acc[3], d);
    }

    // PDL: all of this CTA's globals are written — let k2 begin rolling out
    asm volatile("griddepcontrol.launch_dependents;");
}

// ==== K2: eighth-split survivor scans; finalize deferred to k3 =============
__global__ __launch_bounds__(THR2) void k2() {
    __shared__ float s_mn[THR2 / 32];
    int tid = threadIdx.x, lane = tid & 31, wid = tid >> 5;
    const float INF = __int_as_float(0x7f800000);

    // PDL: wait for k1's memory to be visible (overlaps our launch/prologue)
    asm volatile("griddepcontrol.wait;" ::: "memory");

    // speculative front: sinfo + 8 gt loads + scnt all in flight together
    int b = blockIdx.x;
    int s = b >> 3, part = b & (SPLIT - 1);
    float4 info = g_sinfo[s];                 // garbage slot OK if b>=tot
    const float4* gp = g_gt + part * PARTN + tid;
    float4 g0 = gp[0],        g1 = gp[THR2],     g2 = gp[2 * THR2];
    float4 g3 = gp[3 * THR2], g4 = gp[4 * THR2], g5 = gp[5 * THR2];
    float4 g6 = gp[6 * THR2], g7 = gp[7 * THR2];
    int S = g_scnt;                           // guard only — not an address
    int tot = S * SPLIT;

    float ax = info.x, ay = info.y, az = info.z;
    float mn = fminf(
        fminf(fminf(fchain(ax, ay, az, g0), fchain(ax, ay, az, g1)),
              fminf(fchain(ax, ay, az, g2), fchain(ax, ay, az, g3))),
        fminf(fminf(fchain(ax, ay, az, g4), fchain(ax, ay, az, g5)),
              fminf(fchain(ax, ay, az, g6), fchain(ax, ay, az, g7))));
    #pragma unroll
    for (int off = 16; off; off >>= 1)
        mn = fminf(mn, __shfl_down_sync(0xffffffffu, mn, off));
    if (lane == 0) s_mn[wid] = mn;
    __syncthreads();
    if (tid == 0 && b < tot) {                // publish only if real work
        float m = s_mn[0];
        #pragma unroll
        for (int k = 1; k < THR2 / 32; k++) m = fminf(m, s_mn[k]);
        atomicMin(&g_rmin[s], fmap(m));       // exact, order-preserving
    }

    // overflow path (S > 64): grid-stride, practically never taken
    for (b += CTAS2; b < tot; b += CTAS2) {
        __syncthreads();
        int s2 = b >> 3, p2 = b & (SPLIT - 1);
        float4 in2 = g_sinfo[s2];
        const float4* gq = g_gt + p2 * PARTN + tid;
        float bx = in2.x, by = in2.y, bz = in2.z;
        float a0 = INF, a1 = INF, a2 = INF, a3 = INF;
        #pragma unroll
        for (int jo = 0; jo < PARTN; jo += 4 * THR2) {
            a0 = fminf(a0, fchain(bx, by, bz, gq[jo]));
            a1 = fminf(a1, fchain(bx, by, bz, gq[jo + THR2]));
            a2 = fminf(a2, fchain(bx, by, bz, gq[jo + 2 * THR2]));
            a3 = fminf(a3, fchain(bx, by, bz, gq[jo + 3 * THR2]));
        }
        float m2 = fminf(fminf(a0, a1), fminf(a2, a3));
        #pragma unroll
        for (int off = 16; off; off >>= 1)
            m2 = fminf(m2, __shfl_down_sync(0xffffffffu, m2, off));
        if (lane == 0) s_mn[wid] = m2;
        __syncthreads();
        if (tid == 0) {
            float m = s_mn[0];
            #pragma unroll
            for (int k = 1; k < THR2 / 32; k++) m = fminf(m, s_mn[k]);
            atomicMin(&g_rmin[s2], fmap(m));
        }
    }

    // PDL: this CTA's atomicMin is done — let k3 begin
    asm volatile("griddepcontrol.launch_dependents;");
}

// ==== K3: single-CTA finalize + scratch reset ===============================
__global__ __launch_bounds__(THR3) void k3(float* __restrict__ out) {
    __shared__ float s_f[4][THR3 / 32];
    int tid = threadIdx.x, lane = tid & 31, wid = tid >> 5;

    // PDL: wait for all k2 CTAs' atomicMins to be visible
    asm volatile("griddepcontrol.wait;" ::: "memory");

    int S = g_scnt;
    float s0 = 0.f, s1 = 0.f, c0 = 0.f, c1 = 0.f;
    for (int q = tid; q < S; q += THR3) {
        float4 iq = g_sinfo[q];
        // the part containing j==row reproduced fown exactly ->
        // g_rmin[q] <= fmap(fown); equality <=> nothing strictly closer <=> mask 1
        bool mask = (fmap(iq.w) <= g_rmin[q]);
        float xv = g_sxv[q];
        float lp = log1pf(expf(-fabsf(xv)));
        if (mask) { s1 += fmaxf(-xv, 0.f) + lp; c1 += 1.f; }
        else      { s0 += fmaxf(xv, 0.f) + lp;  c0 += 1.f; }
    }
    #pragma unroll
    for (int off = 16; off; off >>= 1) {
        s0 += __shfl_down_sync(0xffffffffu, s0, off);
        s1 += __shfl_down_sync(0xffffffffu, s1, off);
        c0 += __shfl_down_sync(0xffffffffu, c0, off);
        c1 += __shfl_down_sync(0xffffffffu, c1, off);
    }
    if (lane == 0) {
        s_f[0][wid] = s0; s_f[1][wid] = s1; s_f[2][wid] = c0; s_f[3][wid] = c1;
    }
    __syncthreads();
    if (tid == 0) {
        float t0 = g_acc[2], n0 = g_acc[3], t1 = 0.f, n1 = 0.f;
        #pragma unroll
        for (int k = 0; k < THR3 / 32; k++) {
            t0 += s_f[0][k]; t1 += s_f[1][k]; n0 += s_f[2][k]; n1 += s_f[3][k];
        }
        float sw = g_acc[0], swe = g_acc[1];
        float mean_err = swe / fmaxf(sw, 1e-6f);
        float gr0 = (n0 > 0.f) ? (t0 / fmaxf(n0, 1.f)) : 0.f;
        float gr1 = (n1 > 0.f) ? (t1 / fmaxf(n1, 1.f)) : 0.f;
        out[0] = mean_err + 0.5f * gr0 + 0.5f * gr1;
        // reset cross-launch scratch for next graph replay
        g_scnt = 0;
        #pragma unroll
        for (int k = 0; k < 4; k++) g_acc[k] = 0.f;
        __threadfence();
    }
}

// ---------------- launch: THREE kernels chained by PDL ----------------
extern "C" void kernel_launch(void* const* d_in, const int* in_sizes, int n_in,
                              void* d_out, int out_size) {
    const float* kb = (const float*)d_in[0];   // kp_before       (B,N,3)
    const float* kw = (const float*)d_in[1];   // kp_warped_pred  (B,N,3)
    const float* pg = (const float*)d_in[2];   // pose_gt         (B,3,4)
    const float* ow = (const float*)d_in[3];   // overlap_weights (B,N)
    const float* lg = (const float*)d_in[4];   // inlier_logits   (B,N)
    float* out = (float*)d_out;

    k1<<<CTAS1, THR1>>>(kb, kw, pg, ow, lg);

    cudaLaunchAttribute attrs[1];
    attrs[0].id = cudaLaunchAttributeProgrammaticStreamSerialization;
    attrs[0].val.programmaticStreamSerializationAllowed = 1;

    cudaLaunchConfig_t cfg2 = {};
    cfg2.gridDim = dim3(CTAS2, 1, 1);
    cfg2.blockDim = dim3(THR2, 1, 1);
    cfg2.stream = 0;
    cfg2.attrs = attrs;
    cfg2.numAttrs = 1;
    if (cudaLaunchKernelEx(&cfg2, k2) != cudaSuccess) k2<<<CTAS2, THR2>>>();

    cudaLaunchConfig_t cfg3 = {};
    cfg3.gridDim = dim3(1, 1, 1);
    cfg3.blockDim = dim3(THR3, 1, 1);
    cfg3.stream = 0;
    cfg3.attrs = attrs;
    cfg3.numAttrs = 1;
    if (cudaLaunchKernelEx(&cfg3, k3, out) != cudaSuccess) k3<<<1, THR3>>>(out);
}

// round 17
// speedup vs baseline: 1.0025x; 1.0025x over previous
#include <cuda_runtime.h>

// Problem constants (B=2, N=8192 -> M=16384, fixed for this problem id)
#define MTOT   16384
#define BSHIFT 13
#define CTAS1  64         // k1: 256 rows per CTA, candidates = own 256 rows
#define THR1   256
#define SPLIT  8          // k2: each survivor scanned by 8 CTAs (one part each)
#define PARTN  (MTOT / SPLIT)   // 2048 points per part
#define CTAS2  512
#define THR2   256
#define THR3   256

typedef unsigned long long ull;

// ---------------- scratch (device globals; zero at module load; k3 resets
// the cross-launch counters so graph replays are deterministic) -------------
__device__ float4   g_gt[MTOT];     // gx, gy, gz, |g|^2
__device__ float4   g_sinfo[MTOT];  // survivor: (-2px, -2py, -2pz, fown)
__device__ float    g_sxv[MTOT];    // survivor's logit value
__device__ unsigned g_rmin[MTOT];   // per-survivor global min (ordered uint)
__device__ int      g_scnt;         // survivor count
__device__ float    g_acc[4];       // sum_w, sum_w_err, bce0(phaseA), cnt0(phaseA)

// canonical chain — identical instruction sequence at every use site
__device__ __forceinline__ float fchain(float ax, float ay, float az, float4 g) {
    return fmaf(ax, g.x, fmaf(ay, g.y, fmaf(az, g.z, g.w)));
}
// packed f32x2 helpers (each lane: independent rn-rounded fp32 FMA —
// lane-wise identical to the scalar fchain)
__device__ __forceinline__ ull pack2(float lo, float hi) {
    ull r; asm("mov.b64 %0, {%1, %2};" : "=l"(r) : "f"(lo), "f"(hi)); return r;
}
__device__ __forceinline__ void unpack2(ull v, float& lo, float& hi) {
    asm("mov.b64 {%0, %1}, %2;" : "=f"(lo), "=f"(hi) : "l"(v));
}
__device__ __forceinline__ ull fma2(ull a, ull b, ull c) {
    ull d; asm("fma.rn.f32x2 %0, %1, %2, %3;" : "=l"(d) : "l"(a), "l"(b), "l"(c)); return d;
}
// strictly order-preserving float -> uint map (exact comparisons preserved)
__device__ __forceinline__ unsigned fmap(float f) {
    unsigned u = __float_as_uint(f);
    return (u & 0x80000000u) ? ~u : (u | 0x80000000u);
}

// ==== K1: prep + phase A (own-CTA 256 candidates, SoA + packed f32x2) ======
__global__ __launch_bounds__(THR1) void k1(const float* __restrict__ kb,
                                           const float* __restrict__ kw,
                                           const float* __restrict__ pg,
                                           const float* __restrict__ ow,
                                           const float* __restrict__ lg) {
    __shared__ __align__(16) float s_cx[THR1];   // candidate SoA planes (4 KB)
    __shared__ __align__(16) float s_cy[THR1];
    __shared__ __align__(16) float s_cz[THR1];
    __shared__ __align__(16) float s_cw[THR1];
    __shared__ float s_r4[4][THR1 / 32];
    int tid = threadIdx.x, lane = tid & 31, wid = tid >> 5;
    int row = blockIdx.x * THR1 + tid;       // 32 CTAs per batch, no straddle

    g_rmin[row] = 0xFFFFFFFFu;               // re-arm k2's min slots each launch

    // own row: pose transform (explicit fmaf chain everywhere)
    const float* P = pg + (row >> BSHIFT) * 12;
    float x = kb[3 * row], y = kb[3 * row + 1], z = kb[3 * row + 2];
    float gx = fmaf(P[0], x, fmaf(P[1], y, fmaf(P[2],  z, P[3])));
    float gy = fmaf(P[4], x, fmaf(P[5], y, fmaf(P[6],  z, P[7])));
    float gz = fmaf(P[8], x, fmaf(P[9], y, fmaf(P[10], z, P[11])));
    float sg = fmaf(gx, gx, fmaf(gy, gy, gz * gz));
    float4 gt = make_float4(gx, gy, gz, sg);

    float px = kw[3 * row], py = kw[3 * row + 1], pz = kw[3 * row + 2];
    float ax = -2.0f * px, ay = -2.0f * py, az = -2.0f * pz;
    float fo = fchain(ax, ay, az, gt);

    g_gt[row] = gt;                          // k2's scan table
    s_cx[tid] = gx; s_cy[tid] = gy; s_cz[tid] = gz; s_cw[tid] = sg;

    float w = ow[row];
    float xv = lg[row];
    float swe = w * (fabsf(px - gt.x) + fabsf(py - gt.y) + fabsf(pz - gt.z));
    float sw = w;
    __syncthreads();                         // publish candidate planes

    // phase A, packed FMA + scalar min: 4 candidates per iteration.
    // Lane-wise fma2 nesting == scalar fchain, so own row reproduces fo exactly.
    ull ax2 = pack2(ax, ax), ay2 = pack2(ay, ay), az2 = pack2(az, az);
    const ulonglong2* cx = (const ulonglong2*)s_cx;
    const ulonglong2* cy = (const ulonglong2*)s_cy;
    const ulonglong2* cz = (const ulonglong2*)s_cz;
    const ulonglong2* cw = (const ulonglong2*)s_cw;
    const float INF = __int_as_float(0x7f800000);
    float m0 = INF, m1 = INF, m2 = INF, m3 = INF;
    #pragma unroll 8
    for (int k = 0; k < THR1 / 4; k++) {
        ulonglong2 X = cx[k], Y = cy[k], Z = cz[k], W = cw[k];
        ull d0 = fma2(ax2, X.x, fma2(ay2, Y.x, fma2(az2, Z.x, W.x)));
        ull d1 = fma2(ax2, X.y, fma2(ay2, Y.y, fma2(az2, Z.y, W.y)));
        float a, b, c, d;
        unpack2(d0, a, b);                   // register-pair alias, ~free
        unpack2(d1, c, d);
        m0 = fminf(m0, a); m1 = fminf(m1, b);
        m2 = fminf(m2, c); m3 = fminf(m3, d);
    }
    float mn = fminf(fminf(m0, m1), fminf(m2, m3));

    float s0 = 0.f, c0 = 0.f;
    if (mn < fo) {                           // strictly closer -> mask = 0
        float lp = log1pf(expf(-fabsf(xv)));
        s0 = fmaxf(xv, 0.f) + lp;            // softplus(x), label 0
        c0 = 1.f;
    } else {                                 // unresolved -> exact scan in k2
        int pos = atomicAdd(&g_scnt, 1);
        g_sinfo[pos] = make_float4(ax, ay, az, fo);
        g_sxv[pos] = xv;
    }

    // fused 4-quantity CTA reduction -> one atomicAdd set per CTA
    #pragma unroll
    for (int off = 16; off; off >>= 1) {
        sw  += __shfl_down_sync(0xffffffffu, sw,  off);
        swe += __shfl_down_sync(0xffffffffu, swe, off);
        s0  += __shfl_down_sync(0xffffffffu, s0,  off);
        c0  += __shfl_down_sync(0xffffffffu, c0,  off);
    }
    if (lane == 0) {
        s_r4[0][wid] = sw;  s_r4[1][wid] = swe;
        s_r4[2][wid] = s0;  s_r4[3][wid] = c0;
    }
    __syncthreads();
    if (tid == 0) {
        float a = 0.f, b = 0.f, c = 0.f, d = 0.f;
        #pragma unroll
        for (int k = 0; k < THR1 / 32; k++) {
            a += s_r4[0][k]; b += s_r4[1][k]; c += s_r4[2][k]; d += s_r4[3][k];
        }
        atomicAdd(&g_acc[0], a); atomicAdd(&g_acc[1], b);
        atomicAdd(&g_acc[2], c); atomicAdd(&g_acc[3], d);
    }

    // PDL: all of this CTA's globals are written — let k2 begin rolling out
    asm volatile("griddepcontrol.launch_dependents;");
}

// ==== K2: eighth-split survivor scans; finalize deferred to k3 =============
__global__ __launch_bounds__(THR2) void k2() {
    __shared__ float s_mn[THR2 / 32];
    int tid = threadIdx.x, lane = tid & 31, wid = tid >> 5;
    const float INF = __int_as_float(0x7f800000);

    // PDL: wait for k1's memory to be visible (overlaps our launch/prologue)
    asm volatile("griddepcontrol.wait;" ::: "memory");

    // speculative front: sinfo + 8 gt loads + scnt all in flight together
    int b = blockIdx.x;
    int s = b >> 3, part = b & (SPLIT - 1);
    float4 info = g_sinfo[s];                 // garbage slot OK if b>=tot
    const float4* gp = g_gt + part * PARTN + tid;
    float4 g0 = gp[0],        g1 = gp[THR2],     g2 = gp[2 * THR2];
    float4 g3 = gp[3 * THR2], g4 = gp[4 * THR2], g5 = gp[5 * THR2];
    float4 g6 = gp[6 * THR2], g7 = gp[7 * THR2];
    int S = g_scnt;                           // guard only — not an address
    int tot = S * SPLIT;

    float ax = info.x, ay = info.y, az = info.z;
    float mn = fminf(
        fminf(fminf(fchain(ax, ay, az, g0), fchain(ax, ay, az, g1)),
              fminf(fchain(ax, ay, az, g2), fchain(ax, ay, az, g3))),
        fminf(fminf(fchain(ax, ay, az, g4), fchain(ax, ay, az, g5)),
              fminf(fchain(ax, ay, az, g6), fchain(ax, ay, az, g7))));
    #pragma unroll
    for (int off = 16; off; off >>= 1)
        mn = fminf(mn, __shfl_down_sync(0xffffffffu, mn, off));
    if (lane == 0) s_mn[wid] = mn;
    __syncthreads();
    if (tid == 0 && b < tot) {                // publish only if real work
        float m = s_mn[0];
        #pragma unroll
        for (int k = 1; k < THR2 / 32; k++) m = fminf(m, s_mn[k]);
        atomicMin(&g_rmin[s], fmap(m));       // exact, order-preserving
    }

    // overflow path (S > 64): grid-stride, practically never taken
    for (b += CTAS2; b < tot; b += CTAS2) {
        __syncthreads();
        int s2 = b >> 3, p2 = b & (SPLIT - 1);
        float4 in2 = g_sinfo[s2];
        const float4* gq = g_gt + p2 * PARTN + tid;
        float bx = in2.x, by = in2.y, bz = in2.z;
        float a0 = INF, a1 = INF, a2 = INF, a3 = INF;
        #pragma unroll
        for (int jo = 0; jo < PARTN; jo += 4 * THR2) {
            a0 = fminf(a0, fchain(bx, by, bz, gq[jo]));
            a1 = fminf(a1, fchain(bx, by, bz, gq[jo + THR2]));
            a2 = fminf(a2, fchain(bx, by, bz, gq[jo + 2 * THR2]));
            a3 = fminf(a3, fchain(bx, by, bz, gq[jo + 3 * THR2]));
        }
        float m2 = fminf(fminf(a0, a1), fminf(a2, a3));
        #pragma unroll
        for (int off = 16; off; off >>= 1)
            m2 = fminf(m2, __shfl_down_sync(0xffffffffu, m2, off));
        if (lane == 0) s_mn[wid] = m2;
        __syncthreads();
        if (tid == 0) {
            float m = s_mn[0];
            #pragma unroll
            for (int k = 1; k < THR2 / 32; k++) m = fminf(m, s_mn[k]);
            atomicMin(&g_rmin[s2], fmap(m));
        }
    }

    // PDL: this CTA's atomicMin is done — let k3 begin
    asm volatile("griddepcontrol.launch_dependents;");
}

// ==== K3: single-CTA finalize + scratch reset ===============================
__global__ __launch_bounds__(THR3) void k3(float* __restrict__ out) {
    __shared__ float s_f[4][THR3 / 32];
    int tid = threadIdx.x, lane = tid & 31, wid = tid >> 5;

    // PDL: wait for all k2 CTAs' atomicMins to be visible
    asm volatile("griddepcontrol.wait;" ::: "memory");

    int S = g_scnt;
    float s0 = 0.f, s1 = 0.f, c0 = 0.f, c1 = 0.f;
    for (int q = tid; q < S; q += THR3) {
        float4 iq = g_sinfo[q];
        // the part containing j==row reproduced fown exactly ->
        // g_rmin[q] <= fmap(fown); equality <=> nothing strictly closer <=> mask 1
        bool mask = (fmap(iq.w) <= g_rmin[q]);
        float xv = g_sxv[q];
        float lp = log1pf(expf(-fabsf(xv)));
        if (mask) { s1 += fmaxf(-xv, 0.f) + lp; c1 += 1.f; }
        else      { s0 += fmaxf(xv, 0.f) + lp;  c0 += 1.f; }
    }
    #pragma unroll
    for (int off = 16; off; off >>= 1) {
        s0 += __shfl_down_sync(0xffffffffu, s0, off);
        s1 += __shfl_down_sync(0xffffffffu, s1, off);
        c0 += __shfl_down_sync(0xffffffffu, c0, off);
        c1 += __shfl_down_sync(0xffffffffu, c1, off);
    }
    if (lane == 0) {
        s_f[0][wid] = s0; s_f[1][wid] = s1; s_f[2][wid] = c0; s_f[3][wid] = c1;
    }
    __syncthreads();
    if (tid == 0) {
        float t0 = g_acc[2], n0 = g_acc[3], t1 = 0.f, n1 = 0.f;
        #pragma unroll
        for (int k = 0; k < THR3 / 32; k++) {
            t0 += s_f[0][k]; t1 += s_f[1][k]; n0 += s_f[2][k]; n1 += s_f[3][k];
        }
        float sw = g_acc[0], swe = g_acc[1];
        float mean_err = swe / fmaxf(sw, 1e-6f);
        float gr0 = (n0 > 0.f) ? (t0 / fmaxf(n0, 1.f)) : 0.f;
        float gr1 = (n1 > 0.f) ? (t1 / fmaxf(n1, 1.f)) : 0.f;
        out[0] = mean_err + 0.5f * gr0 + 0.5f * gr1;
        // reset cross-launch scratch for next graph replay
        g_scnt = 0;
        #pragma unroll
        for (int k = 0; k < 4; k++) g_acc[k] = 0.f;
        __threadfence();
    }
}

// ---------------- launch: THREE kernels chained by PDL ----------------
extern "C" void kernel_launch(void* const* d_in, const int* in_sizes, int n_in,
                              void* d_out, int out_size) {
    const float* kb = (const float*)d_in[0];   // kp_before       (B,N,3)
    const float* kw = (const float*)d_in[1];   // kp_warped_pred  (B,N,3)
    const float* pg = (const float*)d_in[2];   // pose_gt         (B,3,4)
    const float* ow = (const float*)d_in[3];   // overlap_weights (B,N)
    const float* lg = (const float*)d_in[4];   // inlier_logits   (B,N)
    float* out = (float*)d_out;

    k1<<<CTAS1, THR1>>>(kb, kw, pg, ow, lg);

    cudaLaunchAttribute attrs[1];
    attrs[0].id = cudaLaunchAttributeProgrammaticStreamSerialization;
    attrs[0].val.programmaticStreamSerializationAllowed = 1;

    cudaLaunchConfig_t cfg2 = {};
    cfg2.gridDim = dim3(CTAS2, 1, 1);
    cfg2.blockDim = dim3(THR2, 1, 1);
    cfg2.stream = 0;
    cfg2.attrs = attrs;
    cfg2.numAttrs = 1;
    if (cudaLaunchKernelEx(&cfg2, k2) != cudaSuccess) k2<<<CTAS2, THR2>>>();

    cudaLaunchConfig_t cfg3 = {};
    cfg3.gridDim = dim3(1, 1, 1);
    cfg3.blockDim = dim3(THR3, 1, 1);
    cfg3.stream = 0;
    cfg3.attrs = attrs;
    cfg3.numAttrs = 1;
    if (cudaLaunchKernelEx(&cfg3, k3, out) != cudaSuccess) k3<<<1, THR3>>>(out);
}